// round 15
// baseline (speedup 1.0000x reference)
#include <cuda_runtime.h>
#include <cuda_fp16.h>
#include <cstdint>

#define NWORDS 8192
#define WLEN   20
#define VOCAB  256
#define E      64
#define H      256
#define H3     768

__device__ __half g_pooledh[NWORDS * H3];   // [word][3H] fp16
__device__ __half g_lwh[H * H3];            // lw in fp16

// ---------------- helpers ----------------
__device__ __forceinline__ unsigned smem_u32(const void* p) {
  return (unsigned)__cvta_generic_to_shared(p);
}
__device__ __forceinline__ unsigned swz(unsigned off) {   // 128B-row swizzle
  return off ^ ((off >> 3) & 0x70);
}
__device__ __forceinline__ void cpasync16(unsigned dst, const void* src) {
  asm volatile("cp.async.cg.shared.global [%0], [%1], 16;" :: "r"(dst), "l"(src));
}
__device__ __forceinline__ void cp_commit() {
  asm volatile("cp.async.commit_group;" ::: "memory");
}
template <int N>
__device__ __forceinline__ void cp_wait() {
  asm volatile("cp.async.wait_group %0;" :: "n"(N) : "memory");
}
__device__ __forceinline__ void ldsm4(uint32_t* r, unsigned addr) {
  asm volatile("ldmatrix.sync.aligned.m8n8.x4.shared.b16 {%0,%1,%2,%3}, [%4];"
               : "=r"(r[0]), "=r"(r[1]), "=r"(r[2]), "=r"(r[3]) : "r"(addr));
}
__device__ __forceinline__ void mma16816(float* d, const uint32_t* a,
                                         uint32_t b0, uint32_t b1) {
  asm volatile(
      "mma.sync.aligned.m16n8k16.row.col.f32.f16.f16.f32 "
      "{%0,%1,%2,%3}, {%4,%5,%6,%7}, {%8,%9}, {%0,%1,%2,%3};"
      : "+f"(d[0]), "+f"(d[1]), "+f"(d[2]), "+f"(d[3])
      : "r"(a[0]), "r"(a[1]), "r"(a[2]), "r"(a[3]), "r"(b0), "r"(b1));
}

// ================= K0: lw -> fp16 (192 blocks, 1 float4/thread) =============
__global__ void __launch_bounds__(256) lwh_kernel(const float* __restrict__ lw) {
  int idx = blockIdx.x * 256 + threadIdx.x;   // < 49152
  float4 v = reinterpret_cast<const float4*>(lw)[idx];
  __half2* dst = reinterpret_cast<__half2*>(g_lwh);
  dst[idx * 2]     = __floats2half2_rn(v.x, v.y);
  dst[idx * 2 + 1] = __floats2half2_rn(v.z, v.w);
}

// ===== K1: persistent conv-as-lookup with fused in-CTA table build v2 =====
// Table rows: 64 fp16 = 128B, ALIGNED (stride 32 half2). Fragments go via a
// stride-36 bounce buffer (conflict-free stores), then row-copy to table.
#define TAPOFF  8192                       // half2 per tap slice (256*32)
#define TILE_W 128
#define CS_BYTES (TILE_W * WLEN * 4)       // 10240 per buffer
#define PA_B1 16
#define W1C   2048
#define PA_B3 48
#define W3C   683
#define PA_B5 84
#define W5C   391
#define NBTOT (PA_B1 + PA_B3 + PA_B5)      // 148
#define TBL_BYTES 163840                   // 5*256*64*2
#define S_EMB_HI 163840
#define S_EMB_LO 172032
#define S_WT_HI  180224
#define S_WT_LO  188416
#define CHARS_OFF 196608                   // bounce (9216B) overlaps chars
#define A_SMEM   (CHARS_OFF + 2 * CS_BYTES)  // 217088

__global__ void __launch_bounds__(512, 1) phase_a_kernel(
    const int* __restrict__ chars, const float* __restrict__ emb,
    const float* __restrict__ w1, const float* __restrict__ w3,
    const float* __restrict__ w5, const float* __restrict__ b1,
    const float* __restrict__ b3, const float* __restrict__ b5) {
  extern __shared__ char smA[];
  __half2* Th = reinterpret_cast<__half2*>(smA);
  const unsigned sbA = smem_u32(smA);

  const int b    = blockIdx.x;
  const int tid  = threadIdx.x;
  const int lane = tid & 31;
  const int warp = tid >> 5;

  int branch, slice, wstart, wend, ntaps;
  if (b < PA_B1) {
    branch = 0; slice = b & 3; int chunk = b >> 2;
    wstart = chunk * W1C; wend = min(wstart + W1C, NWORDS);
    ntaps = 1;
  } else if (b < PA_B1 + PA_B3) {
    int r = b - PA_B1;
    branch = 1; slice = r & 3; int chunk = r >> 2;
    wstart = chunk * W3C; wend = min(wstart + W3C, NWORDS);
    ntaps = 3;
  } else {
    int r = b - PA_B1 - PA_B3;
    branch = 2; slice = r & 3; int chunk = r >> 2;
    wstart = chunk * W5C; wend = min(wstart + W5C, NWORDS);
    ntaps = 5;
  }
  const int h0 = slice * 64;
  const int ntiles = (wend - wstart + TILE_W - 1) / TILE_W;
  const float* wsrc = (branch == 0) ? w1 : ((branch == 1) ? w3 : w5);

  // ======== fused table build: tap-outer, char-quarter inner ========
  // warp tile: M16 (chars) x N16 (h): m0=(warp&3)*16, n0=(warp>>2)*16
  const int m0 = (warp & 3) * 16;
  const int n0 = (warp >> 2) * 16;
  const int rg = lane >> 2;
  const int cg3 = lane & 3;
  __half2* bounce = reinterpret_cast<__half2*>(smA + CHARS_OFF);

  for (int t = 0; t < ntaps; ++t) {
    for (int q = 0; q < 4; ++q) {
      __syncthreads();   // scratch + bounce free
      // stage emb quarter q (64 chars x 64 e), hi/lo — 1 iter/thread
      {
        const float4* emb4 = reinterpret_cast<const float4*>(emb);
        int c = tid >> 3, p = tid & 7;
        float4 u = emb4[(q * 64 + c) * 16 + p * 2];
        float4 v = emb4[(q * 64 + c) * 16 + p * 2 + 1];
        float f[8] = {u.x, u.y, u.z, u.w, v.x, v.y, v.z, v.w};
        __half hi[8], lo[8];
#pragma unroll
        for (int j = 0; j < 8; ++j) {
          hi[j] = __float2half(f[j]);
          lo[j] = __float2half(f[j] - __half2float(hi[j]));
        }
        unsigned off = swz(c * 128 + p * 16);
        *reinterpret_cast<int4*>(smA + S_EMB_HI + off) =
            *reinterpret_cast<int4*>(hi);
        *reinterpret_cast<int4*>(smA + S_EMB_LO + off) =
            *reinterpret_cast<int4*>(lo);
      }
      if (q == 0) {
        // stage weight rows h0..h0+63 x 64e for tap t, hi/lo
        for (int i = tid; i < 4096; i += 512) {
          int h = i >> 6, e = i & 63;
          float v = wsrc[((h0 + h) * E + e) * ntaps + t];
          __half vh = __float2half(v);
          __half vl = __float2half(v - __half2float(vh));
          unsigned off = swz(h * 128 + e * 2);
          *reinterpret_cast<__half*>(smA + S_WT_HI + off) = vh;
          *reinterpret_cast<__half*>(smA + S_WT_LO + off) = vl;
        }
      }
      __syncthreads();

      float acc[2][4];
#pragma unroll
      for (int nt = 0; nt < 2; ++nt)
#pragma unroll
        for (int u = 0; u < 4; ++u) acc[nt][u] = 0.f;

#pragma unroll
      for (int pass = 0; pass < 3; ++pass) {
        const unsigned abase = sbA + ((pass == 1) ? S_EMB_LO : S_EMB_HI);
        const unsigned bbase = sbA + ((pass == 2) ? S_WT_LO : S_WT_HI);
#pragma unroll
        for (int k16 = 0; k16 < 4; ++k16) {
          const unsigned kbyte = k16 * 32 + (lane >> 4) * 16;
          uint32_t a[4];
          ldsm4(a, abase + swz((m0 + (lane & 15)) * 128 + kbyte));
          uint32_t bq[4];
          ldsm4(bq, bbase + swz((n0 + (lane & 15)) * 128 + kbyte));
#pragma unroll
          for (int nt = 0; nt < 2; ++nt)
            mma16816(acc[nt], a, bq[nt], bq[2 + nt]);
        }
      }

      // fragments -> bounce (stride 36 half2: conflict-free)
#pragma unroll
      for (int nt = 0; nt < 2; ++nt) {
        int c2 = (n0 >> 1) + nt * 4 + cg3;
        bounce[(m0 + rg) * 36 + c2] =
            __floats2half2_rn(acc[nt][0], acc[nt][1]);
        bounce[(m0 + rg + 8) * 36 + c2] =
            __floats2half2_rn(acc[nt][2], acc[nt][3]);
      }
      __syncthreads();

      // copy bounce -> table rows (aligned 128B, conflict-free)
      {
        int row = tid >> 3, quad = tid & 7;
        int4 v = *reinterpret_cast<const int4*>(
            smA + CHARS_OFF + row * 144 + quad * 16);
        *reinterpret_cast<int4*>(
            smA + (t * 256 + q * 64 + row) * 128 + quad * 16) = v;
      }
    }
  }
  __syncthreads();   // table complete; chars region free

  const float* bsel = (branch == 0) ? b1 : ((branch == 1) ? b3 : b5);
  const __half2 bias =
      __floats2half2_rn(bsel[h0 + 2 * lane], bsel[h0 + 2 * lane + 1]);
  const __half2 zero = __float2half2_rn(0.f);
  const __half2 ninf = __float2half2_rn(-60000.f);

  // prefetch chars tile 0
  {
    int tn0 = min(TILE_W, wend - wstart);
    unsigned dst = sbA + CHARS_OFF;
    const int4* src = reinterpret_cast<const int4*>(chars + wstart * WLEN);
    for (int i = tid; i < tn0 * 5; i += 512) cpasync16(dst + i * 16, src + i);
  }
  cp_commit();

  for (int ti = 0; ti < ntiles; ++ti) {
    const int t0 = wstart + ti * TILE_W;
    const int tn = min(TILE_W, wend - t0);
    __syncthreads();   // prior tile's readers done
    if (ti + 1 < ntiles) {
      int t1 = t0 + TILE_W;
      int tn1 = min(TILE_W, wend - t1);
      unsigned dst = sbA + CHARS_OFF + ((ti + 1) & 1) * CS_BYTES;
      const int4* src = reinterpret_cast<const int4*>(chars + t1 * WLEN);
      for (int i = tid; i < tn1 * 5; i += 512) cpasync16(dst + i * 16, src + i);
    }
    cp_commit();
    cp_wait<1>();
    __syncthreads();

    const int* csb = reinterpret_cast<const int*>(
        smA + CHARS_OFF + (ti & 1) * CS_BYTES);

    for (int i = warp; i < tn; i += 16) {
      const int4* cw = reinterpret_cast<const int4*>(csb + i * WLEN);
      int4 q0 = cw[0], q1 = cw[1], q2 = cw[2], q3 = cw[3], q4 = cw[4];
      int cc[WLEN];
      cc[0]=q0.x; cc[1]=q0.y; cc[2]=q0.z; cc[3]=q0.w;
      cc[4]=q1.x; cc[5]=q1.y; cc[6]=q1.z; cc[7]=q1.w;
      cc[8]=q2.x; cc[9]=q2.y; cc[10]=q2.z; cc[11]=q2.w;
      cc[12]=q3.x; cc[13]=q3.y; cc[14]=q3.z; cc[15]=q3.w;
      cc[16]=q4.x; cc[17]=q4.y; cc[18]=q4.z; cc[19]=q4.w;
#pragma unroll
      for (int p = 0; p < WLEN; ++p) cc[p] = cc[p] * 32 + lane;

      __half2 m = ninf;
      if (branch == 0) {
#pragma unroll
        for (int p = 0; p < WLEN; ++p) m = __hmax2(m, Th[cc[p]]);
      } else if (branch == 1) {
#pragma unroll
        for (int p = 0; p < WLEN; ++p) {
          __half2 s = Th[TAPOFF + cc[p]];                       // j=1 center
          if (p >= 1)       s = __hadd2(s, Th[cc[p - 1]]);      // j=0
          if (p < WLEN - 1) s = __hadd2(s, Th[2 * TAPOFF + cc[p + 1]]);
          m = __hmax2(m, s);
        }
      } else {
#pragma unroll
        for (int p = 0; p < WLEN; ++p) {
          __half2 s = Th[2 * TAPOFF + cc[p]];                   // j=2 center
          if (p >= 2)       s = __hadd2(s, Th[cc[p - 2]]);
          if (p >= 1)       s = __hadd2(s, Th[TAPOFF + cc[p - 1]]);
          if (p < WLEN - 1) s = __hadd2(s, Th[3 * TAPOFF + cc[p + 1]]);
          if (p < WLEN - 2) s = __hadd2(s, Th[4 * TAPOFF + cc[p + 2]]);
          m = __hmax2(m, s);
        }
      }
      __half2 r = __hmax2(__hadd2(m, bias), zero);
      __half2* op = reinterpret_cast<__half2*>(
          g_pooledh + (size_t)(t0 + i) * H3 + branch * H + h0);
      op[lane] = r;
    }
  }
}

// ================= K2: HMMA GEMM, 128x128 tiles, 3-stage KC=64 =============
#define BM 128
#define BN 128
#define KC 64
#define CHUNKS (H3 / KC)        // 12
#define A_ST 16384
#define B_ST 16384
#define STB  (A_ST + B_ST)      // 32768
#define PB_SMEM (3 * STB)       // 98304

__device__ __forceinline__ void pb_prefetch(unsigned sbase, int tid, int m0,
                                            int h0, int kc) {
  const int kt = kc * KC;
  unsigned abuf = sbase + (kc % 3) * STB;
  unsigned bbuf = abuf + A_ST;
#pragma unroll
  for (int i = 0; i < 2; ++i) {
    int idx = i * 512 + tid;
    int m = idx >> 3, kq = idx & 7;
    cpasync16(abuf + swz(m * 128 + kq * 16),
              g_pooledh + (size_t)(m0 + m) * H3 + kt + kq * 8);
  }
#pragma unroll
  for (int i = 0; i < 2; ++i) {
    int idx = i * 512 + tid;
    int h = idx >> 3, kq = idx & 7;
    cpasync16(bbuf + swz(h * 128 + kq * 16),
              g_lwh + (size_t)(h0 + h) * H3 + kt + kq * 8);
  }
  cp_commit();
}

__global__ void __launch_bounds__(512, 1) phase_b_kernel(
    const float* __restrict__ lb, float* __restrict__ out) {
  extern __shared__ char smB[];
  const unsigned sbase = smem_u32(smB);
  const int tid  = threadIdx.x;
  const int lane = tid & 31;
  const int warp = tid >> 5;
  const int wm   = warp & 3;
  const int wn   = warp >> 2;
  const int m0 = blockIdx.x * BM;
  const int h0 = blockIdx.y * BN;

  float acc[2][4][4];
#pragma unroll
  for (int mt = 0; mt < 2; ++mt)
#pragma unroll
    for (int nt = 0; nt < 4; ++nt)
#pragma unroll
      for (int u = 0; u < 4; ++u) acc[mt][nt][u] = 0.f;

  pb_prefetch(sbase, tid, m0, h0, 0);
  pb_prefetch(sbase, tid, m0, h0, 1);

  for (int kc = 0; kc < CHUNKS; ++kc) {
    cp_wait<1>();
    __syncthreads();

    unsigned abuf = sbase + (kc % 3) * STB;
    unsigned bbuf = abuf + A_ST;
#pragma unroll
    for (int k16 = 0; k16 < 4; ++k16) {
      const unsigned kbyte = k16 * 32 + (lane >> 4) * 16;
      uint32_t a[2][4];
#pragma unroll
      for (int mt = 0; mt < 2; ++mt) {
        unsigned row = wm * 32 + mt * 16 + (lane & 15);
        ldsm4(a[mt], abuf + swz(row * 128 + kbyte));
      }
      uint32_t bq[2][4];
#pragma unroll
      for (int nt2 = 0; nt2 < 2; ++nt2) {
        unsigned row = wn * 32 + nt2 * 16 + (lane & 15);
        ldsm4(bq[nt2], bbuf + swz(row * 128 + kbyte));
      }
#pragma unroll
      for (int mt = 0; mt < 2; ++mt)
#pragma unroll
        for (int nt = 0; nt < 4; ++nt)
          mma16816(acc[mt][nt], a[mt],
                   bq[nt >> 1][nt & 1], bq[nt >> 1][2 + (nt & 1)]);
    }

    if (kc + 2 < CHUNKS) pb_prefetch(sbase, tid, m0, h0, kc + 2);
    else cp_commit();
  }

  const int cg = (lane & 3) * 2;
  const int rg = lane >> 2;
#pragma unroll
  for (int nt = 0; nt < 4; ++nt) {
    const int c = h0 + wn * 32 + nt * 8 + cg;
    float2 lbv = *reinterpret_cast<const float2*>(lb + c);
#pragma unroll
    for (int mt = 0; mt < 2; ++mt) {
      int r = m0 + wm * 32 + mt * 16 + rg;
      float2 v0 = make_float2(acc[mt][nt][0] + lbv.x, acc[mt][nt][1] + lbv.y);
      float2 v1 = make_float2(acc[mt][nt][2] + lbv.x, acc[mt][nt][3] + lbv.y);
      *reinterpret_cast<float2*>(out + (size_t)r * H + c) = v0;
      *reinterpret_cast<float2*>(out + (size_t)(r + 8) * H + c) = v1;
    }
  }
}

// ================= launch =================
extern "C" void kernel_launch(void* const* d_in, const int* in_sizes, int n_in,
                              void* d_out, int out_size) {
  const int*   chars = (const int*)d_in[0];
  const float* emb   = (const float*)d_in[1];
  const float* w1    = (const float*)d_in[2];
  const float* b1    = (const float*)d_in[3];
  const float* w3    = (const float*)d_in[4];
  const float* b3    = (const float*)d_in[5];
  const float* w5    = (const float*)d_in[6];
  const float* b5    = (const float*)d_in[7];
  const float* lw    = (const float*)d_in[8];
  const float* lb    = (const float*)d_in[9];
  float* out = (float*)d_out;

  cudaFuncSetAttribute(phase_a_kernel,
                       cudaFuncAttributeMaxDynamicSharedMemorySize, A_SMEM);
  cudaFuncSetAttribute(phase_b_kernel,
                       cudaFuncAttributeMaxDynamicSharedMemorySize, PB_SMEM);

  lwh_kernel<<<192, 256>>>(lw);
  phase_a_kernel<<<NBTOT, 512, A_SMEM>>>(chars, emb, w1, w3, w5, b1, b3, b5);
  phase_b_kernel<<<dim3(NWORDS / BM, 2), 512, PB_SMEM>>>(lb, out);
}

// round 16
// speedup vs baseline: 1.8810x; 1.8810x over previous
#include <cuda_runtime.h>
#include <cuda_fp16.h>
#include <cstdint>

#define NWORDS 8192
#define WLEN   20
#define VOCAB  256
#define E      64
#define H      256
#define TAPS   9
#define H3     768

typedef unsigned long long ull;

__device__ __half g_Th[TAPS * VOCAB * H];   // [tap][char][h] fp16 tables
__device__ __half g_pooledh[NWORDS * H3];   // [word][3H] fp16
__device__ __half g_lwh[H * H3];            // lw in fp16

// ---------------- helpers ----------------
__device__ __forceinline__ void fma2(ull& d, ull a, ull b) {
  asm("fma.rn.f32x2 %0, %1, %2, %0;" : "+l"(d) : "l"(a), "l"(b));
}
__device__ __forceinline__ float2 u2(ull a) {
  float2 v; asm("mov.b64 {%0, %1}, %2;" : "=f"(v.x), "=f"(v.y) : "l"(a)); return v;
}
__device__ __forceinline__ unsigned smem_u32(const void* p) {
  return (unsigned)__cvta_generic_to_shared(p);
}
__device__ __forceinline__ unsigned swz(unsigned off) {   // 128B-row swizzle
  return off ^ ((off >> 3) & 0x70);
}
__device__ __forceinline__ void cpasync16(unsigned dst, const void* src) {
  asm volatile("cp.async.cg.shared.global [%0], [%1], 16;" :: "r"(dst), "l"(src));
}
__device__ __forceinline__ void cp_commit() {
  asm volatile("cp.async.commit_group;" ::: "memory");
}
template <int N>
__device__ __forceinline__ void cp_wait() {
  asm volatile("cp.async.wait_group %0;" :: "n"(N) : "memory");
}
__device__ __forceinline__ void ldsm4(uint32_t* r, unsigned addr) {
  asm volatile("ldmatrix.sync.aligned.m8n8.x4.shared.b16 {%0,%1,%2,%3}, [%4];"
               : "=r"(r[0]), "=r"(r[1]), "=r"(r[2]), "=r"(r[3]) : "r"(addr));
}
__device__ __forceinline__ void mma16816(float* d, const uint32_t* a,
                                         uint32_t b0, uint32_t b1) {
  asm volatile(
      "mma.sync.aligned.m16n8k16.row.col.f32.f16.f16.f32 "
      "{%0,%1,%2,%3}, {%4,%5,%6,%7}, {%8,%9}, {%0,%1,%2,%3};"
      : "+f"(d[0]), "+f"(d[1]), "+f"(d[2]), "+f"(d[3])
      : "r"(a[0]), "r"(a[1]), "r"(a[2]), "r"(a[3]), "r"(b0), "r"(b1));
}

// ================= K0: build fp16 tables + lw->fp16 (fused; proven) =========
#define EPAD 68
#define WPD  66
#define K0_SMEM ((64 * EPAD + 16 * WPD) * 4)

__global__ void __launch_bounds__(256) build_tables_kernel(
    const float* __restrict__ emb, const float* __restrict__ w1,
    const float* __restrict__ w3, const float* __restrict__ w5,
    const float* __restrict__ lw) {
  const int t   = blockIdx.x;
  const int tid = threadIdx.x;

  if (t == TAPS) {   // lwh conversion
    int bi = blockIdx.y * 4 + blockIdx.z;
    if (bi >= 48) return;
    const float4* src = reinterpret_cast<const float4*>(lw);
    __half2* dst = reinterpret_cast<__half2*>(g_lwh);
#pragma unroll
    for (int i = 0; i < 4; ++i) {
      int idx = (bi * 4 + i) * 256 + tid;
      float4 v = src[idx];
      dst[idx * 2]     = __floats2half2_rn(v.x, v.y);
      dst[idx * 2 + 1] = __floats2half2_rn(v.z, v.w);
    }
    return;
  }

  extern __shared__ float sm0[];
  float* embs = sm0;                 // [64][EPAD]
  float* wts  = sm0 + 64 * EPAD;     // [16][WPD]
  const int h0  = blockIdx.y * 16;
  const int c0  = blockIdx.z * 64;
  const int cl  = tid >> 4;
  const int hl  = tid & 15;

  const float4* emb4 = reinterpret_cast<const float4*>(emb);
#pragma unroll
  for (int i = 0; i < 4; ++i) {
    int idx = i * 256 + tid;
    int c = idx >> 4, e4 = idx & 15;
    float4 v = emb4[(c0 + c) * 16 + e4];
    float* d = embs + c * EPAD + e4 * 4;
    d[0] = v.x; d[1] = v.y; d[2] = v.z; d[3] = v.w;
  }
#pragma unroll
  for (int i = 0; i < 4; ++i) {
    int idx = i * 256 + tid;
    int hh = idx >> 6, e = idx & 63;
    int h = h0 + hh;
    float v;
    if (t == 0)      v = w1[h * E + e];
    else if (t <= 3) v = w3[(h * E + e) * 3 + (t - 1)];
    else             v = w5[(h * E + e) * 5 + (t - 4)];
    wts[hh * WPD + e] = v;
  }
  __syncthreads();

  ull acc2[4];
#pragma unroll
  for (int j = 0; j < 4; ++j) acc2[j] = 0ull;
  const ull* wrow = reinterpret_cast<const ull*>(wts + hl * WPD);
  const ull* eb   = reinterpret_cast<const ull*>(embs);
#pragma unroll 4
  for (int e2 = 0; e2 < E / 2; ++e2) {
    ull w2 = wrow[e2];
#pragma unroll
    for (int j = 0; j < 4; ++j)
      fma2(acc2[j], eb[(cl + 16 * j) * (EPAD / 2) + e2], w2);
  }

  __syncthreads();
  __half* tile = reinterpret_cast<__half*>(sm0);
#pragma unroll
  for (int j = 0; j < 4; ++j) {
    float2 v = u2(acc2[j]);
    tile[(cl + 16 * j) * 16 + hl] = __float2half(v.x + v.y);
  }
  __syncthreads();
  if (tid < 128) {
    int c = tid >> 1, q = tid & 1;
    int4 v = reinterpret_cast<const int4*>(tile)[tid];
    *reinterpret_cast<int4*>(
        g_Th + (size_t)(t * VOCAB + c0 + c) * H + h0 + q * 8) = v;
  }
}

// ===== K1: persistent conv-as-lookup, cp.async table + char staging =====
#define HC 64
#define TILE_W 128
#define CS_BYTES (TILE_W * WLEN * 4)     // 10240 per buffer
#define PA_B1 20
#define W1C   1639
#define PA_B3 48
#define W3C   683
#define PA_B5 80
#define W5C   410
#define NBTOT (PA_B1 + PA_B3 + PA_B5)    // 148
#define A_TBL_BYTES (5 * 256 * HC * 2)   // 163840
#define A_SMEM (A_TBL_BYTES + 2 * CS_BYTES)  // 184320

__global__ void __launch_bounds__(512, 1) phase_a_kernel(
    const int* __restrict__ chars, const float* __restrict__ b1,
    const float* __restrict__ b3, const float* __restrict__ b5) {
  extern __shared__ char smA[];
  __half2* Th = reinterpret_cast<__half2*>(smA);
  const unsigned sbA = smem_u32(smA);

  const int b    = blockIdx.x;
  const int tid  = threadIdx.x;
  const int lane = tid & 31;
  const int warp = tid >> 5;

  int branch, slice, wstart, wend, ntaps, tapg0;
  if (b < PA_B1) {
    branch = 0; slice = b & 3; int chunk = b >> 2;
    wstart = chunk * W1C; wend = min(wstart + W1C, NWORDS);
    ntaps = 1; tapg0 = 0;
  } else if (b < PA_B1 + PA_B3) {
    int r = b - PA_B1;
    branch = 1; slice = r & 3; int chunk = r >> 2;
    wstart = chunk * W3C; wend = min(wstart + W3C, NWORDS);
    ntaps = 3; tapg0 = 1;
  } else {
    int r = b - PA_B1 - PA_B3;
    branch = 2; slice = r & 3; int chunk = r >> 2;
    wstart = chunk * W5C; wend = min(wstart + W5C, NWORDS);
    ntaps = 5; tapg0 = 4;
  }
  const int h0 = slice * HC;
  const int ntiles = (wend - wstart + TILE_W - 1) / TILE_W;

  // prefetch chars tile 0 FIRST (lands under table-staging shadow)
  {
    int tn0 = min(TILE_W, wend - wstart);
    unsigned dst = sbA + A_TBL_BYTES;
    const int4* src = reinterpret_cast<const int4*>(chars + wstart * WLEN);
    for (int i = tid; i < tn0 * 5; i += 512) cpasync16(dst + i * 16, src + i);
  }
  cp_commit();

  // stage table slice via cp.async (once per CTA life)
  {
    const int nf4 = ntaps * 2048;
    for (int i = tid; i < nf4; i += 512) {
      int row = i >> 3, q = i & 7;
      cpasync16(sbA + i * 16,
                reinterpret_cast<const int4*>(
                    g_Th + (size_t)(tapg0 * 256 + row) * H + h0) + q);
    }
  }
  cp_commit();

  const float* bsel = (branch == 0) ? b1 : ((branch == 1) ? b3 : b5);
  const __half2 bias =
      __floats2half2_rn(bsel[h0 + 2 * lane], bsel[h0 + 2 * lane + 1]);
  const __half2 zero = __float2half2_rn(0.f);
  const __half2 ninf = __float2half2_rn(-60000.f);

  for (int ti = 0; ti < ntiles; ++ti) {
    const int t0 = wstart + ti * TILE_W;
    const int tn = min(TILE_W, wend - t0);
    if (ti == 0) {
      cp_wait<0>();         // chars tile0 + table both resident
      __syncthreads();
    } else {
      __syncthreads();      // prior tile's readers done
    }
    if (ti + 1 < ntiles) {
      int t1 = t0 + TILE_W;
      int tn1 = min(TILE_W, wend - t1);
      unsigned dst = sbA + A_TBL_BYTES + ((ti + 1) & 1) * CS_BYTES;
      const int4* src = reinterpret_cast<const int4*>(chars + t1 * WLEN);
      for (int i = tid; i < tn1 * 5; i += 512) cpasync16(dst + i * 16, src + i);
    }
    cp_commit();
    cp_wait<1>();
    __syncthreads();

    const int* csb = reinterpret_cast<const int*>(
        smA + A_TBL_BYTES + (ti & 1) * CS_BYTES);

    for (int i = warp; i < tn; i += 16) {
      const int4* cw = reinterpret_cast<const int4*>(csb + i * WLEN);
      int4 q0 = cw[0], q1 = cw[1], q2 = cw[2], q3 = cw[3], q4 = cw[4];
      int cc[WLEN];
      cc[0]=q0.x; cc[1]=q0.y; cc[2]=q0.z; cc[3]=q0.w;
      cc[4]=q1.x; cc[5]=q1.y; cc[6]=q1.z; cc[7]=q1.w;
      cc[8]=q2.x; cc[9]=q2.y; cc[10]=q2.z; cc[11]=q2.w;
      cc[12]=q3.x; cc[13]=q3.y; cc[14]=q3.z; cc[15]=q3.w;
      cc[16]=q4.x; cc[17]=q4.y; cc[18]=q4.z; cc[19]=q4.w;
#pragma unroll
      for (int p = 0; p < WLEN; ++p) cc[p] = cc[p] * 32 + lane;

      __half2 m = ninf;
      if (branch == 0) {
#pragma unroll
        for (int p = 0; p < WLEN; ++p) m = __hmax2(m, Th[cc[p]]);
      } else if (branch == 1) {
#pragma unroll
        for (int p = 0; p < WLEN; ++p) {
          __half2 s = Th[8192 + cc[p]];
          if (p >= 1)       s = __hadd2(s, Th[cc[p - 1]]);
          if (p < WLEN - 1) s = __hadd2(s, Th[16384 + cc[p + 1]]);
          m = __hmax2(m, s);
        }
      } else {
#pragma unroll
        for (int p = 0; p < WLEN; ++p) {
          __half2 s = Th[16384 + cc[p]];
          if (p >= 2)       s = __hadd2(s, Th[cc[p - 2]]);
          if (p >= 1)       s = __hadd2(s, Th[8192 + cc[p - 1]]);
          if (p < WLEN - 1) s = __hadd2(s, Th[24576 + cc[p + 1]]);
          if (p < WLEN - 2) s = __hadd2(s, Th[32768 + cc[p + 2]]);
          m = __hmax2(m, s);
        }
      }
      __half2 r = __hmax2(__hadd2(m, bias), zero);
      __half2* op = reinterpret_cast<__half2*>(
          g_pooledh + (size_t)(t0 + i) * H3 + branch * H + h0);
      op[lane] = r;
    }
  }
}

// ================= K2: HMMA GEMM, 128x128 tiles, 3-stage KC=64 =============
#define BM 128
#define BN 128
#define KC 64
#define CHUNKS (H3 / KC)        // 12
#define A_ST 16384
#define B_ST 16384
#define STB  (A_ST + B_ST)      // 32768
#define PB_SMEM (3 * STB)       // 98304

__device__ __forceinline__ void pb_prefetch(unsigned sbase, int tid, int m0,
                                            int h0, int kc) {
  const int kt = kc * KC;
  unsigned abuf = sbase + (kc % 3) * STB;
  unsigned bbuf = abuf + A_ST;
#pragma unroll
  for (int i = 0; i < 2; ++i) {
    int idx = i * 512 + tid;
    int m = idx >> 3, kq = idx & 7;
    cpasync16(abuf + swz(m * 128 + kq * 16),
              g_pooledh + (size_t)(m0 + m) * H3 + kt + kq * 8);
  }
#pragma unroll
  for (int i = 0; i < 2; ++i) {
    int idx = i * 512 + tid;
    int h = idx >> 3, kq = idx & 7;
    cpasync16(bbuf + swz(h * 128 + kq * 16),
              g_lwh + (size_t)(h0 + h) * H3 + kt + kq * 8);
  }
  cp_commit();
}

__global__ void __launch_bounds__(512, 1) phase_b_kernel(
    const float* __restrict__ lb, float* __restrict__ out) {
  extern __shared__ char smB[];
  const unsigned sbase = smem_u32(smB);
  const int tid  = threadIdx.x;
  const int lane = tid & 31;
  const int warp = tid >> 5;
  const int wm   = warp & 3;
  const int wn   = warp >> 2;
  const int m0 = blockIdx.x * BM;
  const int h0 = blockIdx.y * BN;

  float acc[2][4][4];
#pragma unroll
  for (int mt = 0; mt < 2; ++mt)
#pragma unroll
    for (int nt = 0; nt < 4; ++nt)
#pragma unroll
      for (int u = 0; u < 4; ++u) acc[mt][nt][u] = 0.f;

  pb_prefetch(sbase, tid, m0, h0, 0);
  pb_prefetch(sbase, tid, m0, h0, 1);

  for (int kc = 0; kc < CHUNKS; ++kc) {
    cp_wait<1>();
    __syncthreads();

    unsigned abuf = sbase + (kc % 3) * STB;
    unsigned bbuf = abuf + A_ST;
#pragma unroll
    for (int k16 = 0; k16 < 4; ++k16) {
      const unsigned kbyte = k16 * 32 + (lane >> 4) * 16;
      uint32_t a[2][4];
#pragma unroll
      for (int mt = 0; mt < 2; ++mt) {
        unsigned row = wm * 32 + mt * 16 + (lane & 15);
        ldsm4(a[mt], abuf + swz(row * 128 + kbyte));
      }
      uint32_t bq[2][4];
#pragma unroll
      for (int nt2 = 0; nt2 < 2; ++nt2) {
        unsigned row = wn * 32 + nt2 * 16 + (lane & 15);
        ldsm4(bq[nt2], bbuf + swz(row * 128 + kbyte));
      }
#pragma unroll
      for (int mt = 0; mt < 2; ++mt)
#pragma unroll
        for (int nt = 0; nt < 4; ++nt)
          mma16816(acc[mt][nt], a[mt],
                   bq[nt >> 1][nt & 1], bq[nt >> 1][2 + (nt & 1)]);
    }

    if (kc + 2 < CHUNKS) pb_prefetch(sbase, tid, m0, h0, kc + 2);
    else cp_commit();
  }

  const int cg = (lane & 3) * 2;
  const int rg = lane >> 2;
#pragma unroll
  for (int nt = 0; nt < 4; ++nt) {
    const int c = h0 + wn * 32 + nt * 8 + cg;
    float2 lbv = *reinterpret_cast<const float2*>(lb + c);
#pragma unroll
    for (int mt = 0; mt < 2; ++mt) {
      int r = m0 + wm * 32 + mt * 16 + rg;
      float2 v0 = make_float2(acc[mt][nt][0] + lbv.x, acc[mt][nt][1] + lbv.y);
      float2 v1 = make_float2(acc[mt][nt][2] + lbv.x, acc[mt][nt][3] + lbv.y);
      *reinterpret_cast<float2*>(out + (size_t)r * H + c) = v0;
      *reinterpret_cast<float2*>(out + (size_t)(r + 8) * H + c) = v1;
    }
  }
}

// ================= launch =================
extern "C" void kernel_launch(void* const* d_in, const int* in_sizes, int n_in,
                              void* d_out, int out_size) {
  const int*   chars = (const int*)d_in[0];
  const float* emb   = (const float*)d_in[1];
  const float* w1    = (const float*)d_in[2];
  const float* b1    = (const float*)d_in[3];
  const float* w3    = (const float*)d_in[4];
  const float* b3    = (const float*)d_in[5];
  const float* w5    = (const float*)d_in[6];
  const float* b5    = (const float*)d_in[7];
  const float* lw    = (const float*)d_in[8];
  const float* lb    = (const float*)d_in[9];
  float* out = (float*)d_out;

  cudaFuncSetAttribute(build_tables_kernel,
                       cudaFuncAttributeMaxDynamicSharedMemorySize, K0_SMEM);
  cudaFuncSetAttribute(phase_a_kernel,
                       cudaFuncAttributeMaxDynamicSharedMemorySize, A_SMEM);
  cudaFuncSetAttribute(phase_b_kernel,
                       cudaFuncAttributeMaxDynamicSharedMemorySize, PB_SMEM);

  build_tables_kernel<<<dim3(TAPS + 1, 16, 4), 256, K0_SMEM>>>(
      emb, w1, w3, w5, lw);
  phase_a_kernel<<<NBTOT, 512, A_SMEM>>>(chars, b1, b3, b5);
  phase_b_kernel<<<dim3(NWORDS / BM, 2), 512, PB_SMEM>>>(lb, out);
}